// round 7
// baseline (speedup 1.0000x reference)
#include <cuda_runtime.h>
#include <cuda_bf16.h>
#include <cuda_fp16.h>
#include <cstdint>

// ---------------------------------------------------------------------------
// Problem constants: B=2, L=2048, D=1024, H=16, hd=64
// ---------------------------------------------------------------------------
#define BATCH 2
#define SEQ   2048
#define DMODEL 1024
#define NHEAD 16
#define HDIM  64
#define MTOT  (BATCH * SEQ)          // 4096
#define CEXPF 0.1803368801111f      // 0.125 * log2(e), folded into q

// Scratch (device globals; no runtime allocation allowed)
__device__ float g_q[MTOT * DMODEL];
__device__ float g_k[MTOT * DMODEL];
__device__ float g_v[MTOT * DMODEL];
__device__ float g_ctx[MTOT * DMODEL];
__device__ float g_xr[MTOT * DMODEL];        // tf32-rounded + k-permuted x
__device__ float g_wq[DMODEL * DMODEL];      // tf32-rounded + k-permuted weights
__device__ float g_wk[DMODEL * DMODEL];
__device__ float g_wv[DMODEL * DMODEL];
__device__ float g_wo[DMODEL * DMODEL];

__device__ __forceinline__ uint32_t f2tf32(float x) {
    uint32_t r;
    asm("cvt.rna.tf32.f32 %0, %1;" : "=r"(r) : "f"(x));
    return r;
}
__device__ __forceinline__ float ex2(float x) {
    float r;
    asm("ex2.approx.f32 %0, %1;" : "=f"(r) : "f"(x));
    return r;
}
__device__ __forceinline__ uint32_t smem_u32(const void* p) {
    uint32_t a;
    asm("{ .reg .u64 t; cvta.to.shared.u64 t, %1; cvt.u32.u64 %0, t; }" : "=r"(a) : "l"(p));
    return a;
}
__device__ __forceinline__ void cp16(uint32_t smem, const float* g) {
    asm volatile("cp.async.cg.shared.global [%0], [%1], 16;"
                 :: "r"(smem), "l"(__cvta_generic_to_global(g)));
}
__device__ __forceinline__ void mma_tf32(float* d, const uint32_t* a, const uint32_t* b) {
    asm volatile(
        "mma.sync.aligned.m16n8k8.row.col.f32.tf32.tf32.f32 "
        "{%0,%1,%2,%3}, {%4,%5,%6,%7}, {%8,%9}, {%0,%1,%2,%3};\n"
        : "+f"(d[0]), "+f"(d[1]), "+f"(d[2]), "+f"(d[3])
        : "r"(a[0]), "r"(a[1]), "r"(a[2]), "r"(a[3]), "r"(b[0]), "r"(b[1]));
}
// k-perm within a 16-group: P(l) = (l&3)*4 + (l>>2)  (involution; 4x4 transpose)
__device__ __forceinline__ int kperm16(int l) {
    return (l & ~15) | (((l & 3) << 2) | ((l >> 2) & 3));
}
__device__ __forceinline__ uint32_t half_bits_to_f32(uint32_t w, bool hi) {
    unsigned short h = hi ? (unsigned short)(w >> 16) : (unsigned short)(w & 0xffff);
    return __float_as_uint(__half2float(__ushort_as_half(h)));
}

// ---------------------------------------------------------------------------
// Fused tf32 round + k-perm of x and all 4 weights (one launch).
// Thread handles one float4 = logicals 16g+4t..16g+4t+3 -> positions 16g+t+4b.
// ---------------------------------------------------------------------------
#define X4 (MTOT * DMODEL / 4)       // 1048576
#define W4 (DMODEL * DMODEL / 4)     // 262144
#define TOTAL4 (X4 + 4 * W4)         // 2097152

__global__ __launch_bounds__(256) void round_perm(
    const float* __restrict__ x, const float* __restrict__ Wq,
    const float* __restrict__ Wk, const float* __restrict__ Wv,
    const float* __restrict__ Wo,
    float* __restrict__ xr, float* __restrict__ wq, float* __restrict__ wk,
    float* __restrict__ wv, float* __restrict__ wo) {
    const int idx = blockIdx.x * 256 + threadIdx.x;
    if (idx >= TOTAL4) return;
    const float* src;
    float* dst;
    int li;
    if (idx < X4) {
        src = x; dst = xr; li = idx;
    } else {
        const int r = idx - X4;
        const int w = r >> 18;           // / W4
        li = r & (W4 - 1);
        switch (w) {
            case 0: src = Wq; dst = wq; break;
            case 1: src = Wk; dst = wk; break;
            case 2: src = Wv; dst = wv; break;
            default: src = Wo; dst = wo; break;
        }
    }
    const int g = li >> 2;
    const int t = li & 3;
    float4 v = reinterpret_cast<const float4*>(src)[li];
    const int base = g * 16 + t;
    dst[base + 0]  = __uint_as_float(f2tf32(v.x));
    dst[base + 4]  = __uint_as_float(f2tf32(v.y));
    dst[base + 8]  = __uint_as_float(f2tf32(v.z));
    dst[base + 12] = __uint_as_float(f2tf32(v.w));
}

// ---------------------------------------------------------------------------
// TF32 mma.sync GEMM over pre-rounded k-permuted inputs.
// C = A @ B^T. CTA 128x128, BK=32, 2-stage cp.async, stride-48 smem
// (conflict-free LDS.128 fragment loads thanks to the k-perm).
// MODE 1 (QKV fused, N=3072): q gets CEXPF scale; q/k get hd-perm on output;
//   all outputs tf32-rounded, scattered to (B,H,L,hd).
// MODE 0 (Wo): plain row-major C.
// ---------------------------------------------------------------------------
#define GK 32
#define GSTR 48
#define GSTAGE (128 * GSTR)                 // floats per operand per stage
#define GSMEM_BYTES (2 * 2 * GSTAGE * 4)    // 98304 B

template <int MODE>
__global__ __launch_bounds__(256, 2) void gemm_mma(const float* __restrict__ A,
                                                   const float* __restrict__ B0,
                                                   const float* __restrict__ B1,
                                                   const float* __restrict__ B2,
                                                   float* __restrict__ C0,
                                                   float* __restrict__ C1,
                                                   float* __restrict__ C2) {
    extern __shared__ float sm[];
    const uint32_t as_a = smem_u32(sm);
    const uint32_t bs_a = as_a + 2 * GSTAGE * 4;

    const int tid = threadIdx.x;
    const int bm = blockIdx.y * 128;
    const int bnab = blockIdx.x * 128;

    const float* B = B0;
    float* C = C0;
    int bn = bnab;
    if (MODE == 1) {
        if (bnab >= 2048)      { B = B2; C = C2; }
        else if (bnab >= 1024) { B = B1; C = C1; }
        bn = bnab & 1023;
    }

    const int wid = tid >> 5;
    const int lane = tid & 31;
    const int wm = (wid & 1) * 64;
    const int wn = (wid >> 1) * 32;
    const int gid = lane >> 2;
    const int tig = lane & 3;

    const int r0c = tid >> 3;           // 0..31
    const int ch0 = tid & 7;            // 16B chunk in 32-float row

    auto issue_chunk = [&](int c, int buf) {
        const uint32_t ab = as_a + (uint32_t)buf * GSTAGE * 4;
        const uint32_t bb = bs_a + (uint32_t)buf * GSTAGE * 4;
        const int k0 = c * GK;
#pragma unroll
        for (int u = 0; u < 4; u++) {
            const int r = r0c + u * 32;
            const uint32_t so = (uint32_t)(r * GSTR + ch0 * 4) * 4;
            cp16(ab + so, A + (size_t)(bm + r) * DMODEL + k0 + ch0 * 4);
            cp16(bb + so, B + (size_t)(bn + r) * DMODEL + k0 + ch0 * 4);
        }
    };

    float acc[4][4][4];
#pragma unroll
    for (int i = 0; i < 4; i++)
#pragma unroll
        for (int j = 0; j < 4; j++)
#pragma unroll
            for (int r = 0; r < 4; r++) acc[i][j][r] = 0.0f;

    const int NCHUNK = DMODEL / GK;     // 32
    issue_chunk(0, 0);
    asm volatile("cp.async.commit_group;");
    issue_chunk(1, 1);
    asm volatile("cp.async.commit_group;");

    for (int c = 0; c < NCHUNK; c++) {
        asm volatile("cp.async.wait_group 1;");
        __syncthreads();

        const int buf = c & 1;
        const float* Asb = sm + buf * GSTAGE;
        const float* Bsb = sm + (2 + buf) * GSTAGE;

#pragma unroll
        for (int g = 0; g < 2; g++) {
            uint4 aF[4][2];
#pragma unroll
            for (int mt = 0; mt < 4; mt++) {
#pragma unroll
                for (int h = 0; h < 2; h++) {
                    aF[mt][h] = *reinterpret_cast<const uint4*>(
                        &Asb[(wm + mt * 16 + gid + 8 * h) * GSTR + g * 16 + 4 * tig]);
                }
            }
#pragma unroll
            for (int nt = 0; nt < 4; nt++) {
                uint4 bF = *reinterpret_cast<const uint4*>(
                    &Bsb[(wn + nt * 8 + gid) * GSTR + g * 16 + 4 * tig]);
                uint32_t b0[2] = {bF.x, bF.y};
                uint32_t b1[2] = {bF.z, bF.w};
#pragma unroll
                for (int mt = 0; mt < 4; mt++) {
                    uint32_t a0[4] = {aF[mt][0].x, aF[mt][1].x, aF[mt][0].y, aF[mt][1].y};
                    mma_tf32(acc[mt][nt], a0, b0);
                    uint32_t a1[4] = {aF[mt][0].z, aF[mt][1].z, aF[mt][0].w, aF[mt][1].w};
                    mma_tf32(acc[mt][nt], a1, b1);
                }
            }
        }
        __syncthreads();

        if (c + 2 < NCHUNK) issue_chunk(c + 2, buf);
        asm volatile("cp.async.commit_group;");
    }

    const bool is_q = (MODE == 1) && (bnab < 1024);
    const bool is_v = (MODE == 1) && (bnab >= 2048);

#pragma unroll
    for (int mt = 0; mt < 4; mt++) {
        const int row0 = bm + wm + mt * 16 + gid;
#pragma unroll
        for (int nt = 0; nt < 4; nt++) {
            const int gcol = bn + wn + nt * 8 + 2 * tig;
#pragma unroll
            for (int half = 0; half < 2; half++) {
                const int row = row0 + 8 * half;
                float v0 = acc[mt][nt][2 * half];
                float v1 = acc[mt][nt][2 * half + 1];
                if (MODE == 0) {
                    *reinterpret_cast<float2*>(C + (size_t)row * DMODEL + gcol) =
                        make_float2(v0, v1);
                } else {
                    const int b = row >> 11;
                    const int l = row & (SEQ - 1);
                    const int h = gcol >> 6;
                    const int dd = gcol & (HDIM - 1);
                    float* dst = C + (((size_t)(b * NHEAD + h) * SEQ) + l) * HDIM;
                    if (is_v) {
                        *reinterpret_cast<uint2*>(dst + dd) =
                            make_uint2(f2tf32(v0), f2tf32(v1));
                    } else {
                        if (is_q) { v0 *= CEXPF; v1 *= CEXPF; }
                        // hd-perm so flash fragment loads are vectorized
                        const int p0 = kperm16(dd);
                        const int p1 = kperm16(dd + 1);
                        *reinterpret_cast<uint32_t*>(dst + p0) = f2tf32(v0);
                        *reinterpret_cast<uint32_t*>(dst + p1) = f2tf32(v1);
                    }
                }
            }
        }
    }
}

// ---------------------------------------------------------------------------
// Flash attention, tf32 mma.sync, causal. Q/K hd-perm'd + q pre-scaled.
// BQ=128 (8 warps x m16), BK=64. Q frags hoisted to registers (loop-invariant).
// K frags via conflict-free LDS.128 (stride 80). P packed f16x2 for shuffles.
// ctx written tf32-rounded + k-perm'd (feeds Wo GEMM).
// ---------------------------------------------------------------------------
#define FA_BK 64
#define FA_QSTR 68
#define FA_KSTR 80
#define FA_VSTR 72
#define FA_SMEM_BYTES ((128 * FA_QSTR + 2 * 64 * FA_KSTR + 2 * 64 * FA_VSTR) * 4)

__device__ __forceinline__ void fa_load_kv(uint32_t ks_a, uint32_t vs_a,
                                           const float* Kg, const float* Vg,
                                           int k0, int stage, int tid) {
    const uint32_t ko = ks_a + (uint32_t)stage * (64 * FA_KSTR * 4);
    const uint32_t vo = vs_a + (uint32_t)stage * (64 * FA_VSTR * 4);
#pragma unroll
    for (int u = 0; u < 4; u++) {
        const int idx = u * 256 + tid;
        const int r = idx >> 4;
        const int ch = idx & 15;
        cp16(ko + (uint32_t)(r * FA_KSTR + ch * 4) * 4, Kg + (size_t)(k0 + r) * HDIM + ch * 4);
        cp16(vo + (uint32_t)(r * FA_VSTR + ch * 4) * 4, Vg + (size_t)(k0 + r) * HDIM + ch * 4);
    }
}

__global__ __launch_bounds__(256, 2) void flash_mma(const float* __restrict__ Q,
                                                    const float* __restrict__ K,
                                                    const float* __restrict__ V,
                                                    float* __restrict__ ctx) {
    extern __shared__ float fs[];
    float* Qs = fs;
    float* Ks = fs + 128 * FA_QSTR;
    float* Vs = fs + 128 * FA_QSTR + 2 * 64 * FA_KSTR;

    const int tid = threadIdx.x;
    const int w = tid >> 5;
    const int lane = tid & 31;
    const int gid = lane >> 2;
    const int tig = lane & 3;
    const int bh = blockIdx.y;
    const int qb = (int)gridDim.x - 1 - (int)blockIdx.x;
    const int q0 = qb * 128;

    const float* Qg = Q + ((size_t)bh * SEQ + q0) * HDIM;
    const float* Kg = K + (size_t)bh * SEQ * HDIM;
    const float* Vg = V + (size_t)bh * SEQ * HDIM;

    const uint32_t qs_a = smem_u32(Qs);
    const uint32_t ks_a = smem_u32(Ks);
    const uint32_t vs_a = smem_u32(Vs);

#pragma unroll
    for (int u = 0; u < 8; u++) {
        const int idx = u * 256 + tid;
        const int r = idx >> 4;
        const int ch = idx & 15;
        cp16(qs_a + (uint32_t)(r * FA_QSTR + ch * 4) * 4, Qg + (size_t)r * HDIM + ch * 4);
    }
    fa_load_kv(ks_a, vs_a, Kg, Vg, 0, 0, tid);
    asm volatile("cp.async.commit_group;");

    float o[8][4];
#pragma unroll
    for (int nt = 0; nt < 8; nt++)
#pragma unroll
        for (int e = 0; e < 4; e++) o[nt][e] = 0.0f;
    float m0 = -1e30f, m1 = -1e30f, l0 = 0.0f, l1 = 0.0f;

    const int nkb = 2 * qb + 2;
    const int rq = 16 * w + gid;
    uint32_t qa_all[8][4];

    for (int kb = 0; kb < nkb; kb++) {
        if (kb + 1 < nkb) {
            fa_load_kv(ks_a, vs_a, Kg, Vg, (kb + 1) * FA_BK, (kb + 1) & 1, tid);
            asm volatile("cp.async.commit_group;");
            asm volatile("cp.async.wait_group 1;");
        } else {
            asm volatile("cp.async.wait_group 0;");
        }
        __syncthreads();

        if (kb == 0) {
            // Q fragments are loop-invariant: hoist to registers once.
#pragma unroll
            for (int g = 0; g < 4; g++) {
                uint4 f0 = *reinterpret_cast<const uint4*>(
                    &Qs[rq * FA_QSTR + g * 16 + 4 * tig]);
                uint4 f1 = *reinterpret_cast<const uint4*>(
                    &Qs[(rq + 8) * FA_QSTR + g * 16 + 4 * tig]);
                qa_all[2 * g][0] = f0.x; qa_all[2 * g][1] = f1.x;
                qa_all[2 * g][2] = f0.y; qa_all[2 * g][3] = f1.y;
                qa_all[2 * g + 1][0] = f0.z; qa_all[2 * g + 1][1] = f1.z;
                qa_all[2 * g + 1][2] = f0.w; qa_all[2 * g + 1][3] = f1.w;
            }
        }

        const float* Ksb = Ks + (kb & 1) * 64 * FA_KSTR;
        const uint32_t* Vsb = reinterpret_cast<const uint32_t*>(Vs + (kb & 1) * 64 * FA_VSTR);

        // --- S = Q K^T (16 x 64 per warp), vectorized K frags ---
        float c[8][4];
#pragma unroll
        for (int nt = 0; nt < 8; nt++)
#pragma unroll
            for (int e = 0; e < 4; e++) c[nt][e] = 0.0f;

#pragma unroll
        for (int g = 0; g < 4; g++) {
#pragma unroll
            for (int nt = 0; nt < 8; nt++) {
                uint4 kF = *reinterpret_cast<const uint4*>(
                    &Ksb[(8 * nt + gid) * FA_KSTR + g * 16 + 4 * tig]);
                uint32_t b0[2] = {kF.x, kF.y};
                mma_tf32(c[nt], qa_all[2 * g], b0);
                uint32_t b1[2] = {kF.z, kF.w};
                mma_tf32(c[nt], qa_all[2 * g + 1], b1);
            }
        }

        // --- causal mask (S already in log2-exp units; scale folded into q) ---
        const int k0 = kb * FA_BK;
        if (k0 + 63 > q0 + 16 * w) {
            const int r0g = q0 + rq;
#pragma unroll
            for (int nt = 0; nt < 8; nt++) {
                const int cb = k0 + 8 * nt + 2 * tig;
                if (cb > r0g) c[nt][0] = -1e30f;
                if (cb + 1 > r0g) c[nt][1] = -1e30f;
                if (cb > r0g + 8) c[nt][2] = -1e30f;
                if (cb + 1 > r0g + 8) c[nt][3] = -1e30f;
            }
        }

        // --- online softmax ---
        float mx0 = -1e30f, mx1 = -1e30f;
#pragma unroll
        for (int nt = 0; nt < 8; nt++) {
            mx0 = fmaxf(mx0, fmaxf(c[nt][0], c[nt][1]));
            mx1 = fmaxf(mx1, fmaxf(c[nt][2], c[nt][3]));
        }
        mx0 = fmaxf(mx0, __shfl_xor_sync(0xffffffffu, mx0, 1));
        mx0 = fmaxf(mx0, __shfl_xor_sync(0xffffffffu, mx0, 2));
        mx1 = fmaxf(mx1, __shfl_xor_sync(0xffffffffu, mx1, 1));
        mx1 = fmaxf(mx1, __shfl_xor_sync(0xffffffffu, mx1, 2));

        const float mn0 = fmaxf(fmaxf(m0, mx0), -1000.0f);
        const float mn1 = fmaxf(fmaxf(m1, mx1), -1000.0f);
        const float corr0 = ex2(m0 - mn0);
        const float corr1 = ex2(m1 - mn1);

        float rs0 = 0.0f, rs1 = 0.0f;
        uint32_t pw[8][2];
#pragma unroll
        for (int nt = 0; nt < 8; nt++) {
            const float p0 = ex2(c[nt][0] - mn0);
            const float p1 = ex2(c[nt][1] - mn0);
            const float p2 = ex2(c[nt][2] - mn1);
            const float p3 = ex2(c[nt][3] - mn1);
            rs0 += p0 + p1;
            rs1 += p2 + p3;
            __half2 h01 = __floats2half2_rn(p0, p1);
            __half2 h23 = __floats2half2_rn(p2, p3);
            pw[nt][0] = *reinterpret_cast<uint32_t*>(&h01);
            pw[nt][1] = *reinterpret_cast<uint32_t*>(&h23);
        }
        rs0 += __shfl_xor_sync(0xffffffffu, rs0, 1);
        rs0 += __shfl_xor_sync(0xffffffffu, rs0, 2);
        rs1 += __shfl_xor_sync(0xffffffffu, rs1, 1);
        rs1 += __shfl_xor_sync(0xffffffffu, rs1, 2);

        l0 = l0 * corr0 + rs0;
        l1 = l1 * corr1 + rs1;
        m0 = mn0;
        m1 = mn1;

#pragma unroll
        for (int nt = 0; nt < 8; nt++) {
            o[nt][0] *= corr0;
            o[nt][1] *= corr0;
            o[nt][2] *= corr1;
            o[nt][3] *= corr1;
        }

        // --- O += P V : packed-half shuffles reshape S-frags -> A-frags ---
        const int srcA = (lane & 28) | (tig >> 1);
        const int srcB = srcA + 2;
        const bool odd = (tig & 1) != 0;
#pragma unroll
        for (int j = 0; j < 8; j++) {
            const uint32_t wA0 = __shfl_sync(0xffffffffu, pw[j][0], srcA);
            const uint32_t wB0 = __shfl_sync(0xffffffffu, pw[j][0], srcB);
            const uint32_t wA1 = __shfl_sync(0xffffffffu, pw[j][1], srcA);
            const uint32_t wB1 = __shfl_sync(0xffffffffu, pw[j][1], srcB);
            uint32_t pa[4];
            pa[0] = half_bits_to_f32(wA0, odd);   // P[gid][8j+tig]
            pa[2] = half_bits_to_f32(wB0, odd);   // P[gid][8j+tig+4]
            pa[1] = half_bits_to_f32(wA1, odd);   // P[gid+8][8j+tig]
            pa[3] = half_bits_to_f32(wB1, odd);   // P[gid+8][8j+tig+4]
#pragma unroll
            for (int nt = 0; nt < 8; nt++) {
                uint32_t vf[2];
                vf[0] = Vsb[(8 * j + tig) * FA_VSTR + 8 * nt + gid];
                vf[1] = Vsb[(8 * j + tig + 4) * FA_VSTR + 8 * nt + gid];
                mma_tf32(o[nt], pa, vf);
            }
        }
        __syncthreads();
    }

    // normalize + write ctx tf32-rounded, k-perm'd, (B, L, D) layout
    const float inv0 = 1.0f / l0;
    const float inv1 = 1.0f / l1;
    const int b = bh >> 4;
    const int h = bh & 15;
    const int r0 = q0 + rq;
#pragma unroll
    for (int nt = 0; nt < 8; nt++) {
        const int lc = 8 * nt + 2 * tig;
        const int p0 = h * HDIM + kperm16(lc);
        const int p1 = h * HDIM + kperm16(lc + 1);
        float* d0 = ctx + ((size_t)(b * SEQ + r0) * DMODEL);
        float* d1 = ctx + ((size_t)(b * SEQ + r0 + 8) * DMODEL);
        *reinterpret_cast<uint32_t*>(d0 + p0) = f2tf32(o[nt][0] * inv0);
        *reinterpret_cast<uint32_t*>(d0 + p1) = f2tf32(o[nt][1] * inv0);
        *reinterpret_cast<uint32_t*>(d1 + p0) = f2tf32(o[nt][2] * inv1);
        *reinterpret_cast<uint32_t*>(d1 + p1) = f2tf32(o[nt][3] * inv1);
    }
}

// ---------------------------------------------------------------------------
// Launch
// ---------------------------------------------------------------------------
static float* sym_addr(const void* symbol) {
    void* p = nullptr;
    cudaGetSymbolAddress(&p, symbol);
    return reinterpret_cast<float*>(p);
}

extern "C" void kernel_launch(void* const* d_in, const int* in_sizes, int n_in,
                              void* d_out, int out_size) {
    const float* x  = (const float*)d_in[0];
    const float* Wq = (const float*)d_in[1];
    const float* Wk = (const float*)d_in[2];
    const float* Wv = (const float*)d_in[3];
    const float* Wo = (const float*)d_in[4];
    float* out = (float*)d_out;

    float* q   = sym_addr(g_q);
    float* k   = sym_addr(g_k);
    float* v   = sym_addr(g_v);
    float* ctx = sym_addr(g_ctx);
    float* xr  = sym_addr(g_xr);
    float* wq  = sym_addr(g_wq);
    float* wk  = sym_addr(g_wk);
    float* wv  = sym_addr(g_wv);
    float* wo  = sym_addr(g_wo);

    cudaFuncSetAttribute(gemm_mma<1>, cudaFuncAttributeMaxDynamicSharedMemorySize, GSMEM_BYTES);
    cudaFuncSetAttribute(gemm_mma<0>, cudaFuncAttributeMaxDynamicSharedMemorySize, GSMEM_BYTES);
    cudaFuncSetAttribute(flash_mma, cudaFuncAttributeMaxDynamicSharedMemorySize, FA_SMEM_BYTES);

    round_perm<<<(TOTAL4 + 255) / 256, 256>>>(x, Wq, Wk, Wv, Wo, xr, wq, wk, wv, wo);

    dim3 gqkv(3 * DMODEL / 128, MTOT / 128);   // (24, 32)
    gemm_mma<1><<<gqkv, 256, GSMEM_BYTES>>>(xr, wq, wk, wv, q, k, v);

    dim3 ga(SEQ / 128, BATCH * NHEAD);         // (16, 32)
    flash_mma<<<ga, 256, FA_SMEM_BYTES>>>(q, k, v, ctx);

    dim3 go(DMODEL / 128, MTOT / 128);         // (8, 32)
    gemm_mma<0><<<go, 256, GSMEM_BYTES>>>(ctx, wo, nullptr, nullptr, out, nullptr, nullptr);
}

// round 8
// speedup vs baseline: 1.0081x; 1.0081x over previous
#include <cuda_runtime.h>
#include <cuda_bf16.h>
#include <cuda_fp16.h>
#include <cstdint>

// ---------------------------------------------------------------------------
// Problem constants: B=2, L=2048, D=1024, H=16, hd=64
// ---------------------------------------------------------------------------
#define BATCH 2
#define SEQ   2048
#define DMODEL 1024
#define NHEAD 16
#define HDIM  64
#define MTOT  (BATCH * SEQ)          // 4096
#define CEXPF 0.1803368801111f      // 0.125 * log2(e), folded into q

// Scratch (device globals; no runtime allocation allowed)
__device__ float g_q[MTOT * DMODEL];
__device__ float g_k[MTOT * DMODEL];
__device__ float g_v[MTOT * DMODEL];
__device__ float g_ctx[MTOT * DMODEL];
__device__ float g_xr[MTOT * DMODEL];
__device__ float g_wq[DMODEL * DMODEL];
__device__ float g_wk[DMODEL * DMODEL];
__device__ float g_wv[DMODEL * DMODEL];
__device__ float g_wo[DMODEL * DMODEL];

__device__ __forceinline__ uint32_t f2tf32(float x) {
    uint32_t r;
    asm("cvt.rna.tf32.f32 %0, %1;" : "=r"(r) : "f"(x));
    return r;
}
__device__ __forceinline__ float ex2(float x) {
    float r;
    asm("ex2.approx.f32 %0, %1;" : "=f"(r) : "f"(x));
    return r;
}
__device__ __forceinline__ uint32_t smem_u32(const void* p) {
    uint32_t a;
    asm("{ .reg .u64 t; cvta.to.shared.u64 t, %1; cvt.u32.u64 %0, t; }" : "=r"(a) : "l"(p));
    return a;
}
__device__ __forceinline__ void cp16(uint32_t smem, const float* g) {
    asm volatile("cp.async.cg.shared.global [%0], [%1], 16;"
                 :: "r"(smem), "l"(__cvta_generic_to_global(g)));
}
__device__ __forceinline__ void mma_tf32(float* d, const uint32_t* a, const uint32_t* b) {
    asm volatile(
        "mma.sync.aligned.m16n8k8.row.col.f32.tf32.tf32.f32 "
        "{%0,%1,%2,%3}, {%4,%5,%6,%7}, {%8,%9}, {%0,%1,%2,%3};\n"
        : "+f"(d[0]), "+f"(d[1]), "+f"(d[2]), "+f"(d[3])
        : "r"(a[0]), "r"(a[1]), "r"(a[2]), "r"(a[3]), "r"(b[0]), "r"(b[1]));
}
// k-perm within a 16-group: P(l) = (l&3)*4 + (l>>2)  (involution)
__device__ __forceinline__ int kperm16(int l) {
    return (l & ~15) | (((l & 3) << 2) | ((l >> 2) & 3));
}
__device__ __forceinline__ uint32_t half_bits_to_f32(uint32_t w, bool hi) {
    unsigned short h = hi ? (unsigned short)(w >> 16) : (unsigned short)(w & 0xffff);
    return __float_as_uint(__half2float(__ushort_as_half(h)));
}

// ---------------------------------------------------------------------------
// Fused tf32 round + k-perm of x and all 4 weights (one launch).
// ---------------------------------------------------------------------------
#define X4 (MTOT * DMODEL / 4)
#define W4 (DMODEL * DMODEL / 4)
#define TOTAL4 (X4 + 4 * W4)

__global__ __launch_bounds__(256) void round_perm(
    const float* __restrict__ x, const float* __restrict__ Wq,
    const float* __restrict__ Wk, const float* __restrict__ Wv,
    const float* __restrict__ Wo,
    float* __restrict__ xr, float* __restrict__ wq, float* __restrict__ wk,
    float* __restrict__ wv, float* __restrict__ wo) {
    const int idx = blockIdx.x * 256 + threadIdx.x;
    if (idx >= TOTAL4) return;
    const float* src;
    float* dst;
    int li;
    if (idx < X4) {
        src = x; dst = xr; li = idx;
    } else {
        const int r = idx - X4;
        const int w = r >> 18;
        li = r & (W4 - 1);
        switch (w) {
            case 0: src = Wq; dst = wq; break;
            case 1: src = Wk; dst = wk; break;
            case 2: src = Wv; dst = wv; break;
            default: src = Wo; dst = wo; break;
        }
    }
    const int g = li >> 2;
    const int t = li & 3;
    float4 v = reinterpret_cast<const float4*>(src)[li];
    const int base = g * 16 + t;
    dst[base + 0]  = __uint_as_float(f2tf32(v.x));
    dst[base + 4]  = __uint_as_float(f2tf32(v.y));
    dst[base + 8]  = __uint_as_float(f2tf32(v.z));
    dst[base + 12] = __uint_as_float(f2tf32(v.w));
}

// ---------------------------------------------------------------------------
// TF32 mma.sync GEMM, 3-stage cp.async, ONE __syncthreads per chunk.
// C = A @ B^T. CTA 128x128, BK=32, GSTR=36 (conflict-free scalar frag LDS).
// MODE 1 (QKV fused, N=3072); MODE 0 (Wo).
// ---------------------------------------------------------------------------
#define GK 32
#define GSTR 36
#define GSTAGE (128 * GSTR)                  // 4608 floats / stage / operand
#define GNST 3
#define GSMEM_BYTES (2 * GNST * GSTAGE * 4)  // 110592 B

template <int MODE>
__global__ __launch_bounds__(256, 2) void gemm_mma(const float* __restrict__ A,
                                                   const float* __restrict__ B0,
                                                   const float* __restrict__ B1,
                                                   const float* __restrict__ B2,
                                                   float* __restrict__ C0,
                                                   float* __restrict__ C1,
                                                   float* __restrict__ C2) {
    extern __shared__ float sm[];
    const uint32_t as_a = smem_u32(sm);
    const uint32_t bs_a = as_a + GNST * GSTAGE * 4;

    const int tid = threadIdx.x;
    const int bm = blockIdx.y * 128;
    const int bnab = blockIdx.x * 128;

    const float* B = B0;
    float* C = C0;
    int bn = bnab;
    if (MODE == 1) {
        if (bnab >= 2048)      { B = B2; C = C2; }
        else if (bnab >= 1024) { B = B1; C = C1; }
        bn = bnab & 1023;
    }

    const int wid = tid >> 5;
    const int lane = tid & 31;
    const int wm = (wid & 1) * 64;
    const int wn = (wid >> 1) * 32;
    const int gid = lane >> 2;
    const int tig = lane & 3;

    const int r0c = tid >> 3;
    const int ch0 = tid & 7;

    auto issue_chunk = [&](int c, int buf) {
        const uint32_t ab = as_a + (uint32_t)buf * GSTAGE * 4;
        const uint32_t bb = bs_a + (uint32_t)buf * GSTAGE * 4;
        const int k0 = c * GK;
#pragma unroll
        for (int u = 0; u < 4; u++) {
            const int r = r0c + u * 32;
            const uint32_t so = (uint32_t)(r * GSTR + ch0 * 4) * 4;
            cp16(ab + so, A + (size_t)(bm + r) * DMODEL + k0 + ch0 * 4);
            cp16(bb + so, B + (size_t)(bn + r) * DMODEL + k0 + ch0 * 4);
        }
    };

    float acc[4][4][4];
#pragma unroll
    for (int i = 0; i < 4; i++)
#pragma unroll
        for (int j = 0; j < 4; j++)
#pragma unroll
            for (int r = 0; r < 4; r++) acc[i][j][r] = 0.0f;

    const int NCHUNK = DMODEL / GK;          // 32
    issue_chunk(0, 0);
    asm volatile("cp.async.commit_group;");
    issue_chunk(1, 1);
    asm volatile("cp.async.commit_group;");

    for (int c = 0; c < NCHUNK; c++) {
        asm volatile("cp.async.wait_group 1;");
        __syncthreads();
        // safe: top sync ordered all warps past compute(c-1); target buf is (c-1)%3
        if (c + 2 < NCHUNK) issue_chunk(c + 2, (c + 2) % GNST);
        asm volatile("cp.async.commit_group;");

        const int buf = c % GNST;
        const uint32_t* Asb = reinterpret_cast<const uint32_t*>(sm + buf * GSTAGE);
        const uint32_t* Bsb = reinterpret_cast<const uint32_t*>(sm + (GNST + buf) * GSTAGE);

#pragma unroll
        for (int kk = 0; kk < GK; kk += 8) {
            uint32_t af[4][4], bf[4][2];
#pragma unroll
            for (int mt = 0; mt < 4; mt++) {
                const int row = wm + mt * 16;
                af[mt][0] = Asb[(row + gid) * GSTR + kk + tig];
                af[mt][1] = Asb[(row + gid + 8) * GSTR + kk + tig];
                af[mt][2] = Asb[(row + gid) * GSTR + kk + tig + 4];
                af[mt][3] = Asb[(row + gid + 8) * GSTR + kk + tig + 4];
            }
#pragma unroll
            for (int nt = 0; nt < 4; nt++) {
                const int col = wn + nt * 8;
                bf[nt][0] = Bsb[(col + gid) * GSTR + kk + tig];
                bf[nt][1] = Bsb[(col + gid) * GSTR + kk + tig + 4];
            }
#pragma unroll
            for (int mt = 0; mt < 4; mt++)
#pragma unroll
                for (int nt = 0; nt < 4; nt++) mma_tf32(acc[mt][nt], af[mt], bf[nt]);
        }
    }

    const bool is_q = (MODE == 1) && (bnab < 1024);
    const bool is_v = (MODE == 1) && (bnab >= 2048);

#pragma unroll
    for (int mt = 0; mt < 4; mt++) {
        const int row0 = bm + wm + mt * 16 + gid;
#pragma unroll
        for (int nt = 0; nt < 4; nt++) {
            const int gcol = bn + wn + nt * 8 + 2 * tig;
#pragma unroll
            for (int half = 0; half < 2; half++) {
                const int row = row0 + 8 * half;
                float v0 = acc[mt][nt][2 * half];
                float v1 = acc[mt][nt][2 * half + 1];
                if (MODE == 0) {
                    *reinterpret_cast<float2*>(C + (size_t)row * DMODEL + gcol) =
                        make_float2(v0, v1);
                } else {
                    const int b = row >> 11;
                    const int l = row & (SEQ - 1);
                    const int h = gcol >> 6;
                    const int dd = gcol & (HDIM - 1);
                    float* dst = C + (((size_t)(b * NHEAD + h) * SEQ) + l) * HDIM;
                    if (is_v) {
                        *reinterpret_cast<uint2*>(dst + dd) =
                            make_uint2(f2tf32(v0), f2tf32(v1));
                    } else {
                        if (is_q) { v0 *= CEXPF; v1 *= CEXPF; }
                        const int p0 = kperm16(dd);
                        const int p1 = kperm16(dd + 1);
                        *reinterpret_cast<uint32_t*>(dst + p0) = f2tf32(v0);
                        *reinterpret_cast<uint32_t*>(dst + p1) = f2tf32(v1);
                    }
                }
            }
        }
    }
}

// ---------------------------------------------------------------------------
// Flash attention, tf32 mma.sync, causal. Q direct gmem->regs (no Q smem),
// 3-stage cp.async K/V ring, ONE __syncthreads per kb.
// Q/K hd-perm'd + q pre-scaled; ctx written tf32-rounded + k-perm'd.
// ---------------------------------------------------------------------------
#define FA_BK 64
#define FA_KSTR 80
#define FA_VSTR 68
#define FA_KST (64 * FA_KSTR)
#define FA_VST (64 * FA_VSTR)
#define FA_SMEM_BYTES (3 * (FA_KST + FA_VST) * 4)   // 113664 B

__device__ __forceinline__ void fa_load_kv(uint32_t ks_a, uint32_t vs_a,
                                           const float* Kg, const float* Vg,
                                           int k0, int stage, int tid) {
    const uint32_t ko = ks_a + (uint32_t)stage * (FA_KST * 4);
    const uint32_t vo = vs_a + (uint32_t)stage * (FA_VST * 4);
#pragma unroll
    for (int u = 0; u < 4; u++) {
        const int idx = u * 256 + tid;
        const int r = idx >> 4;
        const int ch = idx & 15;
        cp16(ko + (uint32_t)(r * FA_KSTR + ch * 4) * 4, Kg + (size_t)(k0 + r) * HDIM + ch * 4);
        cp16(vo + (uint32_t)(r * FA_VSTR + ch * 4) * 4, Vg + (size_t)(k0 + r) * HDIM + ch * 4);
    }
}

__global__ __launch_bounds__(256, 2) void flash_mma(const float* __restrict__ Q,
                                                    const float* __restrict__ K,
                                                    const float* __restrict__ V,
                                                    float* __restrict__ ctx) {
    extern __shared__ float fs[];
    float* Ks = fs;
    float* Vs = fs + 3 * FA_KST;

    const int tid = threadIdx.x;
    const int w = tid >> 5;
    const int lane = tid & 31;
    const int gid = lane >> 2;
    const int tig = lane & 3;
    const int bh = blockIdx.y;
    const int qb = (int)gridDim.x - 1 - (int)blockIdx.x;
    const int q0 = qb * 128;

    const float* Qg = Q + ((size_t)bh * SEQ + q0) * HDIM;
    const float* Kg = K + (size_t)bh * SEQ * HDIM;
    const float* Vg = V + (size_t)bh * SEQ * HDIM;

    const uint32_t ks_a = smem_u32(Ks);
    const uint32_t vs_a = smem_u32(Vs);

    const int nkb = 2 * qb + 2;
    const int rq = 16 * w + gid;

    // K/V pipeline prologue (2 stages in flight)
    fa_load_kv(ks_a, vs_a, Kg, Vg, 0, 0, tid);
    asm volatile("cp.async.commit_group;");
    if (nkb > 1) fa_load_kv(ks_a, vs_a, Kg, Vg, FA_BK, 1, tid);
    asm volatile("cp.async.commit_group;");

    // Q fragments: loop-invariant, straight from gmem to registers
    uint32_t qa_all[8][4];
#pragma unroll
    for (int g = 0; g < 4; g++) {
        uint4 f0 = *reinterpret_cast<const uint4*>(Qg + rq * HDIM + g * 16 + 4 * tig);
        uint4 f1 = *reinterpret_cast<const uint4*>(Qg + (rq + 8) * HDIM + g * 16 + 4 * tig);
        qa_all[2 * g][0] = f0.x; qa_all[2 * g][1] = f1.x;
        qa_all[2 * g][2] = f0.y; qa_all[2 * g][3] = f1.y;
        qa_all[2 * g + 1][0] = f0.z; qa_all[2 * g + 1][1] = f1.z;
        qa_all[2 * g + 1][2] = f0.w; qa_all[2 * g + 1][3] = f1.w;
    }

    float o[8][4];
#pragma unroll
    for (int nt = 0; nt < 8; nt++)
#pragma unroll
        for (int e = 0; e < 4; e++) o[nt][e] = 0.0f;
    float m0 = -1e30f, m1 = -1e30f, l0 = 0.0f, l1 = 0.0f;

    for (int kb = 0; kb < nkb; kb++) {
        asm volatile("cp.async.wait_group 1;");
        __syncthreads();
        // safe: sync ordered all warps past compute(kb-1); target buf is (kb-1)%3
        if (kb + 2 < nkb) fa_load_kv(ks_a, vs_a, Kg, Vg, (kb + 2) * FA_BK, (kb + 2) % 3, tid);
        asm volatile("cp.async.commit_group;");

        const int buf = kb % 3;
        const float* Ksb = Ks + buf * FA_KST;
        const uint32_t* Vsb = reinterpret_cast<const uint32_t*>(Vs + buf * FA_VST);

        // --- S = Q K^T (16 x 64 per warp) ---
        float c[8][4];
#pragma unroll
        for (int nt = 0; nt < 8; nt++)
#pragma unroll
            for (int e = 0; e < 4; e++) c[nt][e] = 0.0f;

#pragma unroll
        for (int g = 0; g < 4; g++) {
#pragma unroll
            for (int nt = 0; nt < 8; nt++) {
                uint4 kF = *reinterpret_cast<const uint4*>(
                    &Ksb[(8 * nt + gid) * FA_KSTR + g * 16 + 4 * tig]);
                uint32_t b0[2] = {kF.x, kF.y};
                mma_tf32(c[nt], qa_all[2 * g], b0);
                uint32_t b1[2] = {kF.z, kF.w};
                mma_tf32(c[nt], qa_all[2 * g + 1], b1);
            }
        }

        // --- causal mask (log2-units; scale pre-folded into q) ---
        const int k0 = kb * FA_BK;
        if (k0 + 63 > q0 + 16 * w) {
            const int r0g = q0 + rq;
#pragma unroll
            for (int nt = 0; nt < 8; nt++) {
                const int cb = k0 + 8 * nt + 2 * tig;
                if (cb > r0g) c[nt][0] = -1e30f;
                if (cb + 1 > r0g) c[nt][1] = -1e30f;
                if (cb > r0g + 8) c[nt][2] = -1e30f;
                if (cb + 1 > r0g + 8) c[nt][3] = -1e30f;
            }
        }

        // --- online softmax ---
        float mx0 = -1e30f, mx1 = -1e30f;
#pragma unroll
        for (int nt = 0; nt < 8; nt++) {
            mx0 = fmaxf(mx0, fmaxf(c[nt][0], c[nt][1]));
            mx1 = fmaxf(mx1, fmaxf(c[nt][2], c[nt][3]));
        }
        mx0 = fmaxf(mx0, __shfl_xor_sync(0xffffffffu, mx0, 1));
        mx0 = fmaxf(mx0, __shfl_xor_sync(0xffffffffu, mx0, 2));
        mx1 = fmaxf(mx1, __shfl_xor_sync(0xffffffffu, mx1, 1));
        mx1 = fmaxf(mx1, __shfl_xor_sync(0xffffffffu, mx1, 2));

        const float mn0 = fmaxf(fmaxf(m0, mx0), -1000.0f);
        const float mn1 = fmaxf(fmaxf(m1, mx1), -1000.0f);
        const float corr0 = ex2(m0 - mn0);
        const float corr1 = ex2(m1 - mn1);

        float rs0 = 0.0f, rs1 = 0.0f;
        uint32_t pw[8][2];
#pragma unroll
        for (int nt = 0; nt < 8; nt++) {
            const float p0 = ex2(c[nt][0] - mn0);
            const float p1 = ex2(c[nt][1] - mn0);
            const float p2 = ex2(c[nt][2] - mn1);
            const float p3 = ex2(c[nt][3] - mn1);
            rs0 += p0 + p1;
            rs1 += p2 + p3;
            __half2 h01 = __floats2half2_rn(p0, p1);
            __half2 h23 = __floats2half2_rn(p2, p3);
            pw[nt][0] = *reinterpret_cast<uint32_t*>(&h01);
            pw[nt][1] = *reinterpret_cast<uint32_t*>(&h23);
        }
        rs0 += __shfl_xor_sync(0xffffffffu, rs0, 1);
        rs0 += __shfl_xor_sync(0xffffffffu, rs0, 2);
        rs1 += __shfl_xor_sync(0xffffffffu, rs1, 1);
        rs1 += __shfl_xor_sync(0xffffffffu, rs1, 2);

        l0 = l0 * corr0 + rs0;
        l1 = l1 * corr1 + rs1;
        m0 = mn0;
        m1 = mn1;

#pragma unroll
        for (int nt = 0; nt < 8; nt++) {
            o[nt][0] *= corr0;
            o[nt][1] *= corr0;
            o[nt][2] *= corr1;
            o[nt][3] *= corr1;
        }

        // --- O += P V ---
        const int srcA = (lane & 28) | (tig >> 1);
        const int srcB = srcA + 2;
        const bool odd = (tig & 1) != 0;
#pragma unroll
        for (int j = 0; j < 8; j++) {
            const uint32_t wA0 = __shfl_sync(0xffffffffu, pw[j][0], srcA);
            const uint32_t wB0 = __shfl_sync(0xffffffffu, pw[j][0], srcB);
            const uint32_t wA1 = __shfl_sync(0xffffffffu, pw[j][1], srcA);
            const uint32_t wB1 = __shfl_sync(0xffffffffu, pw[j][1], srcB);
            uint32_t pa[4];
            pa[0] = half_bits_to_f32(wA0, odd);
            pa[2] = half_bits_to_f32(wB0, odd);
            pa[1] = half_bits_to_f32(wA1, odd);
            pa[3] = half_bits_to_f32(wB1, odd);
#pragma unroll
            for (int nt = 0; nt < 8; nt++) {
                uint32_t vf[2];
                vf[0] = Vsb[(8 * j + tig) * FA_VSTR + 8 * nt + gid];
                vf[1] = Vsb[(8 * j + tig + 4) * FA_VSTR + 8 * nt + gid];
                mma_tf32(o[nt], pa, vf);
            }
        }
        // no trailing sync: next iteration's top sync provides the ordering
    }

    // normalize + write ctx tf32-rounded, k-perm'd, (B, L, D) layout
    const float inv0 = 1.0f / l0;
    const float inv1 = 1.0f / l1;
    const int b = bh >> 4;
    const int h = bh & 15;
    const int r0 = q0 + rq;
#pragma unroll
    for (int nt = 0; nt < 8; nt++) {
        const int lc = 8 * nt + 2 * tig;
        const int p0 = h * HDIM + kperm16(lc);
        const int p1 = h * HDIM + kperm16(lc + 1);
        float* d0 = ctx + ((size_t)(b * SEQ + r0) * DMODEL);
        float* d1 = ctx + ((size_t)(b * SEQ + r0 + 8) * DMODEL);
        *reinterpret_cast<uint32_t*>(d0 + p0) = f2tf32(o[nt][0] * inv0);
        *reinterpret_cast<uint32_t*>(d0 + p1) = f2tf32(o[nt][1] * inv0);
        *reinterpret_cast<uint32_t*>(d1 + p0) = f2tf32(o[nt][2] * inv1);
        *reinterpret_cast<uint32_t*>(d1 + p1) = f2tf32(o[nt][3] * inv1);
    }
}

// ---------------------------------------------------------------------------
// Launch
// ---------------------------------------------------------------------------
static float* sym_addr(const void* symbol) {
    void* p = nullptr;
    cudaGetSymbolAddress(&p, symbol);
    return reinterpret_cast<float*>(p);
}

extern "C" void kernel_launch(void* const* d_in, const int* in_sizes, int n_in,
                              void* d_out, int out_size) {
    const float* x  = (const float*)d_in[0];
    const float* Wq = (const float*)d_in[1];
    const float* Wk = (const float*)d_in[2];
    const float* Wv = (const float*)d_in[3];
    const float* Wo = (const float*)d_in[4];
    float* out = (float*)d_out;

    float* q   = sym_addr(g_q);
    float* k   = sym_addr(g_k);
    float* v   = sym_addr(g_v);
    float* ctx = sym_addr(g_ctx);
    float* xr  = sym_addr(g_xr);
    float* wq  = sym_addr(g_wq);
    float* wk  = sym_addr(g_wk);
    float* wv  = sym_addr(g_wv);
    float* wo  = sym_addr(g_wo);

    cudaFuncSetAttribute(gemm_mma<1>, cudaFuncAttributeMaxDynamicSharedMemorySize, GSMEM_BYTES);
    cudaFuncSetAttribute(gemm_mma<0>, cudaFuncAttributeMaxDynamicSharedMemorySize, GSMEM_BYTES);
    cudaFuncSetAttribute(flash_mma, cudaFuncAttributeMaxDynamicSharedMemorySize, FA_SMEM_BYTES);

    round_perm<<<(TOTAL4 + 255) / 256, 256>>>(x, Wq, Wk, Wv, Wo, xr, wq, wk, wv, wo);

    dim3 gqkv(3 * DMODEL / 128, MTOT / 128);   // (24, 32)
    gemm_mma<1><<<gqkv, 256, GSMEM_BYTES>>>(xr, wq, wk, wv, q, k, v);

    dim3 ga(SEQ / 128, BATCH * NHEAD);         // (16, 32)
    flash_mma<<<ga, 256, FA_SMEM_BYTES>>>(q, k, v, ctx);

    dim3 go(DMODEL / 128, MTOT / 128);         // (8, 32)
    gemm_mma<0><<<go, 256, GSMEM_BYTES>>>(ctx, wo, nullptr, nullptr, out, nullptr, nullptr);
}

// round 9
// speedup vs baseline: 1.9601x; 1.9444x over previous
#include <cuda_runtime.h>
#include <cuda_fp16.h>
#include <cstdint>

// ---------------------------------------------------------------------------
// Problem constants: B=2, L=2048, D=1024, H=16, hd=64
// ---------------------------------------------------------------------------
#define BATCH 2
#define SEQ   2048
#define DMODEL 1024
#define NHEAD 16
#define HDIM  64
#define MTOT  (BATCH * SEQ)          // 4096
#define CEXPF 0.1803368801111f       // 0.125 * log2(e), folded into q
#define DW32  (DMODEL / 2)           // 512 uint32 (half2) per row

// Scratch (device globals). All fp16 operands stored half2-packed as uint32.
__device__ uint32_t g_xr[MTOT * DW32];
__device__ uint32_t g_wq[DMODEL * DW32];
__device__ uint32_t g_wk[DMODEL * DW32];
__device__ uint32_t g_wv[DMODEL * DW32];
__device__ uint32_t g_wo[DMODEL * DW32];
__device__ uint32_t g_q[MTOT * DMODEL / 2];    // [b*16+h][l][32 u32]
__device__ uint32_t g_k[MTOT * DMODEL / 2];
__device__ uint16_t g_vt[MTOT * DMODEL];       // [b*16+h][hd][l] halves
__device__ uint32_t g_ctx[MTOT * DW32];        // [b*SEQ+l][512 u32]

__device__ __forceinline__ float ex2(float x) {
    float r;
    asm("ex2.approx.f32 %0, %1;" : "=f"(r) : "f"(x));
    return r;
}
__device__ __forceinline__ uint32_t smem_u32(const void* p) {
    uint32_t a;
    asm("{ .reg .u64 t; cvta.to.shared.u64 t, %1; cvt.u32.u64 %0, t; }" : "=r"(a) : "l"(p));
    return a;
}
__device__ __forceinline__ void cp16(uint32_t smem, const void* g) {
    asm volatile("cp.async.cg.shared.global [%0], [%1], 16;"
                 :: "r"(smem), "l"(__cvta_generic_to_global(g)));
}
__device__ __forceinline__ void mma_f16(float* d, const uint32_t* a, const uint32_t* b) {
    asm volatile(
        "mma.sync.aligned.m16n8k16.row.col.f32.f16.f16.f32 "
        "{%0,%1,%2,%3}, {%4,%5,%6,%7}, {%8,%9}, {%0,%1,%2,%3};\n"
        : "+f"(d[0]), "+f"(d[1]), "+f"(d[2]), "+f"(d[3])
        : "r"(a[0]), "r"(a[1]), "r"(a[2]), "r"(a[3]), "r"(b[0]), "r"(b[1]));
}
__device__ __forceinline__ uint32_t h2bits(float a, float b) {
    __half2 h = __floats2half2_rn(a, b);
    return *reinterpret_cast<uint32_t*>(&h);
}
__device__ __forceinline__ uint16_t hbits(float a) {
    __half h = __float2half_rn(a);
    return *reinterpret_cast<uint16_t*>(&h);
}

// ---------------------------------------------------------------------------
// Fused fp16 round+pack of x and all 4 weights (one launch).
// ---------------------------------------------------------------------------
#define X4 (MTOT * DMODEL / 4)
#define W4 (DMODEL * DMODEL / 4)
#define TOTAL4 (X4 + 4 * W4)

__global__ __launch_bounds__(256) void round_pack(
    const float* __restrict__ x, const float* __restrict__ Wq,
    const float* __restrict__ Wk, const float* __restrict__ Wv,
    const float* __restrict__ Wo) {
    const int idx = blockIdx.x * 256 + threadIdx.x;
    if (idx >= TOTAL4) return;
    const float* src;
    uint2* dst;
    int li;
    if (idx < X4) {
        src = x; dst = reinterpret_cast<uint2*>(g_xr); li = idx;
    } else {
        const int r = idx - X4;
        const int w = r >> 18;
        li = r & (W4 - 1);
        switch (w) {
            case 0: src = Wq; dst = reinterpret_cast<uint2*>(g_wq); break;
            case 1: src = Wk; dst = reinterpret_cast<uint2*>(g_wk); break;
            case 2: src = Wv; dst = reinterpret_cast<uint2*>(g_wv); break;
            default: src = Wo; dst = reinterpret_cast<uint2*>(g_wo); break;
        }
    }
    float4 v = reinterpret_cast<const float4*>(src)[li];
    dst[li] = make_uint2(h2bits(v.x, v.y), h2bits(v.z, v.w));
}

// ---------------------------------------------------------------------------
// FP16 mma.sync GEMM: C = A @ B^T over half2-packed inputs.
// CTA 128x128, chunk = 64 halves (32 u32), 3-stage cp.async, one sync/chunk.
// Stride 36 u32 (conflict-free scalar frag LDS, proven pattern).
// MODE 1 (QKV fused, N=3072): q scaled+packed, k packed, v -> transposed half.
// MODE 0 (Wo): fp32 row-major C.
// ---------------------------------------------------------------------------
#define GSTR 36
#define GSTAGE (128 * GSTR)                  // u32 per operand per stage
#define GNST 3
#define GSMEM_BYTES (2 * GNST * GSTAGE * 4)  // 110592 B
#define GNCHUNK 16                           // 1024 halves / 64

template <int MODE>
__global__ __launch_bounds__(256, 2) void gemm_mma(const uint32_t* __restrict__ A,
                                                   const uint32_t* __restrict__ B0,
                                                   const uint32_t* __restrict__ B1,
                                                   const uint32_t* __restrict__ B2,
                                                   float* __restrict__ Cf,
                                                   uint32_t* __restrict__ Cq,
                                                   uint32_t* __restrict__ Ck,
                                                   uint16_t* __restrict__ Cvt) {
    extern __shared__ uint32_t sm32[];
    const uint32_t as_a = smem_u32(sm32);
    const uint32_t bs_a = as_a + GNST * GSTAGE * 4;

    const int tid = threadIdx.x;
    const int bm = blockIdx.y * 128;
    const int bnab = blockIdx.x * 128;

    const uint32_t* B = B0;
    int bn = bnab;
    if (MODE == 1) {
        if (bnab >= 2048)      B = B2;
        else if (bnab >= 1024) B = B1;
        bn = bnab & 1023;
    }

    const int wid = tid >> 5;
    const int lane = tid & 31;
    const int wm = (wid & 1) * 64;
    const int wn = (wid >> 1) * 32;
    const int gid = lane >> 2;
    const int tig = lane & 3;

    const int r0c = tid >> 3;            // 0..31
    const int ch0 = tid & 7;             // 16B chunk in 128B row-chunk

    auto issue_chunk = [&](int c, int buf) {
        const uint32_t ab = as_a + (uint32_t)buf * GSTAGE * 4;
        const uint32_t bb = bs_a + (uint32_t)buf * GSTAGE * 4;
        const int k0 = c * 32;           // u32 offset
#pragma unroll
        for (int u = 0; u < 4; u++) {
            const int r = r0c + u * 32;
            const uint32_t so = (uint32_t)(r * GSTR + ch0 * 4) * 4;
            cp16(ab + so, A + (size_t)(bm + r) * DW32 + k0 + ch0 * 4);
            cp16(bb + so, B + (size_t)(bn + r) * DW32 + k0 + ch0 * 4);
        }
    };

    float acc[4][4][4];
#pragma unroll
    for (int i = 0; i < 4; i++)
#pragma unroll
        for (int j = 0; j < 4; j++)
#pragma unroll
            for (int r = 0; r < 4; r++) acc[i][j][r] = 0.0f;

    issue_chunk(0, 0);
    asm volatile("cp.async.commit_group;");
    issue_chunk(1, 1);
    asm volatile("cp.async.commit_group;");

    for (int c = 0; c < GNCHUNK; c++) {
        asm volatile("cp.async.wait_group 1;");
        __syncthreads();
        if (c + 2 < GNCHUNK) issue_chunk(c + 2, (c + 2) % GNST);
        asm volatile("cp.async.commit_group;");

        const int buf = c % GNST;
        const uint32_t* Asb = sm32 + buf * GSTAGE;
        const uint32_t* Bsb = sm32 + (GNST + buf) * GSTAGE;

#pragma unroll
        for (int kk = 0; kk < 32; kk += 8) {   // 4 k16-steps per chunk
            uint32_t af[4][4], bf[4][2];
#pragma unroll
            for (int mt = 0; mt < 4; mt++) {
                const int row = wm + mt * 16;
                af[mt][0] = Asb[(row + gid) * GSTR + kk + tig];
                af[mt][1] = Asb[(row + gid + 8) * GSTR + kk + tig];
                af[mt][2] = Asb[(row + gid) * GSTR + kk + tig + 4];
                af[mt][3] = Asb[(row + gid + 8) * GSTR + kk + tig + 4];
            }
#pragma unroll
            for (int nt = 0; nt < 4; nt++) {
                const int col = wn + nt * 8;
                bf[nt][0] = Bsb[(col + gid) * GSTR + kk + tig];
                bf[nt][1] = Bsb[(col + gid) * GSTR + kk + tig + 4];
            }
#pragma unroll
            for (int mt = 0; mt < 4; mt++)
#pragma unroll
                for (int nt = 0; nt < 4; nt++) mma_f16(acc[mt][nt], af[mt], bf[nt]);
        }
    }

    const bool is_q = (MODE == 1) && (bnab < 1024);
    const bool is_v = (MODE == 1) && (bnab >= 2048);

#pragma unroll
    for (int mt = 0; mt < 4; mt++) {
        const int row0 = bm + wm + mt * 16 + gid;
#pragma unroll
        for (int nt = 0; nt < 4; nt++) {
            const int gcol = bn + wn + nt * 8 + 2 * tig;   // even
#pragma unroll
            for (int half = 0; half < 2; half++) {
                const int row = row0 + 8 * half;
                float v0 = acc[mt][nt][2 * half];
                float v1 = acc[mt][nt][2 * half + 1];
                if (MODE == 0) {
                    *reinterpret_cast<float2*>(Cf + (size_t)row * DMODEL + gcol) =
                        make_float2(v0, v1);
                } else {
                    const int b = row >> 11;
                    const int l = row & (SEQ - 1);
                    const int h = gcol >> 6;
                    const int dd = gcol & (HDIM - 1);
                    const int bh = b * NHEAD + h;
                    if (is_v) {
                        // transposed half V: [bh][hd][l]
                        Cvt[((size_t)bh * HDIM + dd) * SEQ + l] = hbits(v0);
                        Cvt[((size_t)bh * HDIM + dd + 1) * SEQ + l] = hbits(v1);
                    } else {
                        if (is_q) { v0 *= CEXPF; v1 *= CEXPF; }
                        uint32_t* dst = (is_q ? Cq : Ck);
                        dst[((size_t)bh * SEQ + l) * 32 + (dd >> 1)] = h2bits(v0, v1);
                    }
                }
            }
        }
    }
}

// ---------------------------------------------------------------------------
// Flash attention, fp16 mma.sync m16n8k16, causal.
// Q direct gmem->regs; 3-stage K / V^T cp.async ring, one sync per kb.
// PV A-fragments are the thread's own packed P registers (no shuffles).
// ctx written half2-packed (feeds Wo GEMM directly).
// ---------------------------------------------------------------------------
#define FA_BK 64
#define FA_STR 36                       // u32 stride (32 payload + 4 pad)
#define FA_ST (64 * FA_STR)             // u32 per stage (K or V^T)
#define FA_SMEM_BYTES (6 * FA_ST * 4)   // 55296 B

__device__ __forceinline__ void fa_load_kv(uint32_t ks_a, uint32_t vs_a,
                                           const uint32_t* Kg, const uint16_t* Vtg,
                                           int k0, int stage, int tid) {
    const uint32_t ko = ks_a + (uint32_t)stage * (FA_ST * 4);
    const uint32_t vo = vs_a + (uint32_t)stage * (FA_ST * 4);
#pragma unroll
    for (int u = 0; u < 2; u++) {
        const int idx = u * 256 + tid;
        const int r = idx >> 3;          // 0..63
        const int ch = idx & 7;          // 16B chunk
        cp16(ko + (uint32_t)(r * FA_STR + ch * 4) * 4,
             Kg + (size_t)(k0 + r) * 32 + ch * 4);
        cp16(vo + (uint32_t)(r * FA_STR + ch * 4) * 4,
             Vtg + (size_t)r * SEQ + k0 + ch * 8);
    }
}

__global__ __launch_bounds__(256, 2) void flash_mma(const uint32_t* __restrict__ Q,
                                                    const uint32_t* __restrict__ K,
                                                    const uint16_t* __restrict__ Vt,
                                                    uint32_t* __restrict__ ctx) {
    extern __shared__ uint32_t fs32[];
    uint32_t* Ks = fs32;
    uint32_t* Vs = fs32 + 3 * FA_ST;

    const int tid = threadIdx.x;
    const int w = tid >> 5;
    const int lane = tid & 31;
    const int gid = lane >> 2;
    const int tig = lane & 3;
    const int bh = blockIdx.y;
    const int qb = (int)gridDim.x - 1 - (int)blockIdx.x;
    const int q0 = qb * 128;

    const uint32_t* Qg = Q + ((size_t)bh * SEQ + q0) * 32;
    const uint32_t* Kg = K + (size_t)bh * SEQ * 32;
    const uint16_t* Vtg = Vt + (size_t)bh * HDIM * SEQ;

    const uint32_t ks_a = smem_u32(Ks);
    const uint32_t vs_a = smem_u32(Vs);

    const int nkb = 2 * qb + 2;
    const int rq = 16 * w + gid;

    fa_load_kv(ks_a, vs_a, Kg, Vtg, 0, 0, tid);
    asm volatile("cp.async.commit_group;");
    if (nkb > 1) fa_load_kv(ks_a, vs_a, Kg, Vtg, FA_BK, 1, tid);
    asm volatile("cp.async.commit_group;");

    // Q fragments (loop-invariant): 4 k16-groups, 4 regs each
    uint32_t qa_all[4][4];
#pragma unroll
    for (int g = 0; g < 4; g++) {
        qa_all[g][0] = Qg[(size_t)rq * 32 + 8 * g + tig];
        qa_all[g][1] = Qg[(size_t)(rq + 8) * 32 + 8 * g + tig];
        qa_all[g][2] = Qg[(size_t)rq * 32 + 8 * g + tig + 4];
        qa_all[g][3] = Qg[(size_t)(rq + 8) * 32 + 8 * g + tig + 4];
    }

    float o[8][4];
#pragma unroll
    for (int nt = 0; nt < 8; nt++)
#pragma unroll
        for (int e = 0; e < 4; e++) o[nt][e] = 0.0f;
    float m0 = -1e30f, m1 = -1e30f, l0 = 0.0f, l1 = 0.0f;

    for (int kb = 0; kb < nkb; kb++) {
        asm volatile("cp.async.wait_group 1;");
        __syncthreads();
        if (kb + 2 < nkb) fa_load_kv(ks_a, vs_a, Kg, Vtg, (kb + 2) * FA_BK, (kb + 2) % 3, tid);
        asm volatile("cp.async.commit_group;");

        const int buf = kb % 3;
        const uint32_t* Ksb = Ks + buf * FA_ST;
        const uint32_t* Vsb = Vs + buf * FA_ST;

        // --- S = Q K^T (16 x 64 per warp): 4 k16-steps x 8 key-groups ---
        float c[8][4];
#pragma unroll
        for (int nt = 0; nt < 8; nt++)
#pragma unroll
            for (int e = 0; e < 4; e++) c[nt][e] = 0.0f;

#pragma unroll
        for (int g = 0; g < 4; g++) {
#pragma unroll
            for (int nt = 0; nt < 8; nt++) {
                uint32_t kf[2];
                kf[0] = Ksb[(8 * nt + gid) * FA_STR + 8 * g + tig];
                kf[1] = Ksb[(8 * nt + gid) * FA_STR + 8 * g + tig + 4];
                mma_f16(c[nt], qa_all[g], kf);
            }
        }

        // --- causal mask (log2-units; scale pre-folded into q) ---
        const int k0 = kb * FA_BK;
        if (k0 + 63 > q0 + 16 * w) {
            const int r0g = q0 + rq;
#pragma unroll
            for (int nt = 0; nt < 8; nt++) {
                const int cb = k0 + 8 * nt + 2 * tig;
                if (cb > r0g) c[nt][0] = -1e30f;
                if (cb + 1 > r0g) c[nt][1] = -1e30f;
                if (cb > r0g + 8) c[nt][2] = -1e30f;
                if (cb + 1 > r0g + 8) c[nt][3] = -1e30f;
            }
        }

        // --- online softmax ---
        float mx0 = -1e30f, mx1 = -1e30f;
#pragma unroll
        for (int nt = 0; nt < 8; nt++) {
            mx0 = fmaxf(mx0, fmaxf(c[nt][0], c[nt][1]));
            mx1 = fmaxf(mx1, fmaxf(c[nt][2], c[nt][3]));
        }
        mx0 = fmaxf(mx0, __shfl_xor_sync(0xffffffffu, mx0, 1));
        mx0 = fmaxf(mx0, __shfl_xor_sync(0xffffffffu, mx0, 2));
        mx1 = fmaxf(mx1, __shfl_xor_sync(0xffffffffu, mx1, 1));
        mx1 = fmaxf(mx1, __shfl_xor_sync(0xffffffffu, mx1, 2));

        const float mn0 = fmaxf(fmaxf(m0, mx0), -1000.0f);
        const float mn1 = fmaxf(fmaxf(m1, mx1), -1000.0f);
        const float corr0 = ex2(m0 - mn0);
        const float corr1 = ex2(m1 - mn1);

        float rs0 = 0.0f, rs1 = 0.0f;
        uint32_t pw[8][2];   // [nt][0]: row gid keys 8nt+2tig..+1 ; [1]: row gid+8
#pragma unroll
        for (int nt = 0; nt < 8; nt++) {
            const float p0 = ex2(c[nt][0] - mn0);
            const float p1 = ex2(c[nt][1] - mn0);
            const float p2 = ex2(c[nt][2] - mn1);
            const float p3 = ex2(c[nt][3] - mn1);
            rs0 += p0 + p1;
            rs1 += p2 + p3;
            pw[nt][0] = h2bits(p0, p1);
            pw[nt][1] = h2bits(p2, p3);
        }
        rs0 += __shfl_xor_sync(0xffffffffu, rs0, 1);
        rs0 += __shfl_xor_sync(0xffffffffu, rs0, 2);
        rs1 += __shfl_xor_sync(0xffffffffu, rs1, 1);
        rs1 += __shfl_xor_sync(0xffffffffu, rs1, 2);

        l0 = l0 * corr0 + rs0;
        l1 = l1 * corr1 + rs1;
        m0 = mn0;
        m1 = mn1;

#pragma unroll
        for (int nt = 0; nt < 8; nt++) {
            o[nt][0] *= corr0;
            o[nt][1] *= corr0;
            o[nt][2] *= corr1;
            o[nt][3] *= corr1;
        }

        // --- O += P V : A-frags are own registers; B from V^T smem ---
#pragma unroll
        for (int j = 0; j < 4; j++) {     // k16-step over keys
            uint32_t pa[4] = {pw[2 * j][0], pw[2 * j][1],
                              pw[2 * j + 1][0], pw[2 * j + 1][1]};
#pragma unroll
            for (int nt = 0; nt < 8; nt++) {
                uint32_t vf[2];
                vf[0] = Vsb[(8 * nt + gid) * FA_STR + 8 * j + tig];
                vf[1] = Vsb[(8 * nt + gid) * FA_STR + 8 * j + tig + 4];
                mma_f16(o[nt], pa, vf);
            }
        }
    }

    // normalize + write ctx half2-packed, (B, L, D/2) layout
    const float inv0 = 1.0f / l0;
    const float inv1 = 1.0f / l1;
    const int b = bh >> 4;
    const int h = bh & 15;
    const int r0 = q0 + rq;
#pragma unroll
    for (int nt = 0; nt < 8; nt++) {
        const int ci = h * 32 + 4 * nt + tig;
        ctx[((size_t)(b * SEQ + r0)) * DW32 + ci] = h2bits(o[nt][0] * inv0, o[nt][1] * inv0);
        ctx[((size_t)(b * SEQ + r0 + 8)) * DW32 + ci] = h2bits(o[nt][2] * inv1, o[nt][3] * inv1);
    }
}

// ---------------------------------------------------------------------------
// Launch
// ---------------------------------------------------------------------------
template <typename T>
static T* sym_addr(const void* symbol) {
    void* p = nullptr;
    cudaGetSymbolAddress(&p, symbol);
    return reinterpret_cast<T*>(p);
}

extern "C" void kernel_launch(void* const* d_in, const int* in_sizes, int n_in,
                              void* d_out, int out_size) {
    const float* x  = (const float*)d_in[0];
    const float* Wq = (const float*)d_in[1];
    const float* Wk = (const float*)d_in[2];
    const float* Wv = (const float*)d_in[3];
    const float* Wo = (const float*)d_in[4];
    float* out = (float*)d_out;

    uint32_t* xr = sym_addr<uint32_t>(g_xr);
    uint32_t* wq = sym_addr<uint32_t>(g_wq);
    uint32_t* wk = sym_addr<uint32_t>(g_wk);
    uint32_t* wv = sym_addr<uint32_t>(g_wv);
    uint32_t* wo = sym_addr<uint32_t>(g_wo);
    uint32_t* q  = sym_addr<uint32_t>(g_q);
    uint32_t* k  = sym_addr<uint32_t>(g_k);
    uint16_t* vt = sym_addr<uint16_t>(g_vt);
    uint32_t* ctx = sym_addr<uint32_t>(g_ctx);

    cudaFuncSetAttribute(gemm_mma<1>, cudaFuncAttributeMaxDynamicSharedMemorySize, GSMEM_BYTES);
    cudaFuncSetAttribute(gemm_mma<0>, cudaFuncAttributeMaxDynamicSharedMemorySize, GSMEM_BYTES);
    cudaFuncSetAttribute(flash_mma, cudaFuncAttributeMaxDynamicSharedMemorySize, FA_SMEM_BYTES);

    round_pack<<<(TOTAL4 + 255) / 256, 256>>>(x, Wq, Wk, Wv, Wo);

    dim3 gqkv(3 * DMODEL / 128, MTOT / 128);   // (24, 32)
    gemm_mma<1><<<gqkv, 256, GSMEM_BYTES>>>(xr, wq, wk, wv, nullptr, q, k, vt);

    dim3 ga(SEQ / 128, BATCH * NHEAD);         // (16, 32)
    flash_mma<<<ga, 256, FA_SMEM_BYTES>>>(q, k, vt, ctx);

    dim3 go(DMODEL / 128, MTOT / 128);         // (8, 32)
    gemm_mma<0><<<go, 256, GSMEM_BYTES>>>(ctx, wo, nullptr, nullptr, out, nullptr, nullptr, nullptr);
}

// round 10
// speedup vs baseline: 2.0410x; 1.0413x over previous
#include <cuda_runtime.h>
#include <cuda_fp16.h>
#include <cstdint>

// ---------------------------------------------------------------------------
// Problem constants: B=2, L=2048, D=1024, H=16, hd=64
// ---------------------------------------------------------------------------
#define BATCH 2
#define SEQ   2048
#define DMODEL 1024
#define NHEAD 16
#define HDIM  64
#define MTOT  (BATCH * SEQ)          // 4096
#define CEXPF 0.1803368801111f       // 0.125 * log2(e), folded into q
#define DW32  (DMODEL / 2)           // 512 uint32 (half2) per row

// Scratch (device globals). All fp16 operands stored half2-packed as uint32.
__device__ uint32_t g_xr[MTOT * DW32];
__device__ uint32_t g_wq[DMODEL * DW32];
__device__ uint32_t g_wk[DMODEL * DW32];
__device__ uint32_t g_wv[DMODEL * DW32];
__device__ uint32_t g_wo[DMODEL * DW32];
__device__ uint32_t g_q[MTOT * DMODEL / 2];    // [b*16+h][l][32 u32]
__device__ uint32_t g_k[MTOT * DMODEL / 2];
__device__ uint16_t g_vt[MTOT * DMODEL];       // [b*16+h][hd][l] halves
__device__ uint32_t g_ctx[MTOT * DW32];        // [b*SEQ+l][512 u32]

__device__ __forceinline__ float ex2(float x) {
    float r;
    asm("ex2.approx.f32 %0, %1;" : "=f"(r) : "f"(x));
    return r;
}
__device__ __forceinline__ uint32_t smem_u32(const void* p) {
    uint32_t a;
    asm("{ .reg .u64 t; cvta.to.shared.u64 t, %1; cvt.u32.u64 %0, t; }" : "=r"(a) : "l"(p));
    return a;
}
__device__ __forceinline__ void cp16(uint32_t smem, const void* g) {
    asm volatile("cp.async.cg.shared.global [%0], [%1], 16;"
                 :: "r"(smem), "l"(__cvta_generic_to_global(g)));
}
__device__ __forceinline__ void mma_f16(float* d, const uint32_t* a, const uint32_t* b) {
    asm volatile(
        "mma.sync.aligned.m16n8k16.row.col.f32.f16.f16.f32 "
        "{%0,%1,%2,%3}, {%4,%5,%6,%7}, {%8,%9}, {%0,%1,%2,%3};\n"
        : "+f"(d[0]), "+f"(d[1]), "+f"(d[2]), "+f"(d[3])
        : "r"(a[0]), "r"(a[1]), "r"(a[2]), "r"(a[3]), "r"(b[0]), "r"(b[1]));
}
__device__ __forceinline__ void ldsm4(uint32_t& r0, uint32_t& r1, uint32_t& r2,
                                      uint32_t& r3, uint32_t a) {
    asm volatile("ldmatrix.sync.aligned.m8n8.x4.shared.b16 {%0,%1,%2,%3}, [%4];"
                 : "=r"(r0), "=r"(r1), "=r"(r2), "=r"(r3) : "r"(a));
}
__device__ __forceinline__ uint32_t h2bits(float a, float b) {
    __half2 h = __floats2half2_rn(a, b);
    return *reinterpret_cast<uint32_t*>(&h);
}
__device__ __forceinline__ uint16_t hbits(float a) {
    __half h = __float2half_rn(a);
    return *reinterpret_cast<uint16_t*>(&h);
}

// ---------------------------------------------------------------------------
// Fused fp16 round+pack of x and all 4 weights (one launch).
// ---------------------------------------------------------------------------
#define X4 (MTOT * DMODEL / 4)
#define W4 (DMODEL * DMODEL / 4)
#define TOTAL4 (X4 + 4 * W4)

__global__ __launch_bounds__(256) void round_pack(
    const float* __restrict__ x, const float* __restrict__ Wq,
    const float* __restrict__ Wk, const float* __restrict__ Wv,
    const float* __restrict__ Wo) {
    const int idx = blockIdx.x * 256 + threadIdx.x;
    if (idx >= TOTAL4) return;
    const float* src;
    uint2* dst;
    int li;
    if (idx < X4) {
        src = x; dst = reinterpret_cast<uint2*>(g_xr); li = idx;
    } else {
        const int r = idx - X4;
        const int w = r >> 18;
        li = r & (W4 - 1);
        switch (w) {
            case 0: src = Wq; dst = reinterpret_cast<uint2*>(g_wq); break;
            case 1: src = Wk; dst = reinterpret_cast<uint2*>(g_wk); break;
            case 2: src = Wv; dst = reinterpret_cast<uint2*>(g_wv); break;
            default: src = Wo; dst = reinterpret_cast<uint2*>(g_wo); break;
        }
    }
    float4 v = reinterpret_cast<const float4*>(src)[li];
    dst[li] = make_uint2(h2bits(v.x, v.y), h2bits(v.z, v.w));
}

// ---------------------------------------------------------------------------
// FP16 mma.sync GEMM: C = A @ B^T over half2-packed inputs.
// CTA 128x128, chunk = 64 halves, 3-stage cp.async, one sync/chunk.
// Fragments via ldmatrix.x4 (stride-36 u32 layout is LDSM-conflict-free),
// explicitly double-buffered across k16-steps to hide LDS latency.
// MODE 1 (QKV fused, N=3072); MODE 0 (Wo).
// ---------------------------------------------------------------------------
#define GSTR 36
#define GSTAGE (128 * GSTR)
#define GNST 3
#define GSMEM_BYTES (2 * GNST * GSTAGE * 4)  // 110592 B
#define GNCHUNK 16

template <int MODE>
__global__ __launch_bounds__(256, 2) void gemm_mma(const uint32_t* __restrict__ A,
                                                   const uint32_t* __restrict__ B0,
                                                   const uint32_t* __restrict__ B1,
                                                   const uint32_t* __restrict__ B2,
                                                   float* __restrict__ Cf,
                                                   uint32_t* __restrict__ Cq,
                                                   uint32_t* __restrict__ Ck,
                                                   uint16_t* __restrict__ Cvt) {
    extern __shared__ uint32_t sm32[];
    const uint32_t as_a = smem_u32(sm32);
    const uint32_t bs_a = as_a + GNST * GSTAGE * 4;

    const int tid = threadIdx.x;
    const int bm = blockIdx.y * 128;
    const int bnab = blockIdx.x * 128;

    const uint32_t* B = B0;
    int bn = bnab;
    if (MODE == 1) {
        if (bnab >= 2048)      B = B2;
        else if (bnab >= 1024) B = B1;
        bn = bnab & 1023;
    }

    const int wid = tid >> 5;
    const int lane = tid & 31;
    const int wm = (wid & 1) * 64;
    const int wn = (wid >> 1) * 32;
    const int gid = lane >> 2;
    const int tig = lane & 3;

    // LDSM lane->address mapping (u32 units within a tile row)
    const int a_lrow = (lane & 7) + ((lane >> 3) & 1) * 8;
    const int a_lcol = (lane >> 4) * 4;
    const int b_lrow = (lane & 7) + (lane >> 4) * 8;
    const int b_lcol = ((lane >> 3) & 1) * 4;

    const int r0c = tid >> 3;
    const int ch0 = tid & 7;

    auto issue_chunk = [&](int c, int buf) {
        const uint32_t ab = as_a + (uint32_t)buf * GSTAGE * 4;
        const uint32_t bb = bs_a + (uint32_t)buf * GSTAGE * 4;
        const int k0 = c * 32;
#pragma unroll
        for (int u = 0; u < 4; u++) {
            const int r = r0c + u * 32;
            const uint32_t so = (uint32_t)(r * GSTR + ch0 * 4) * 4;
            cp16(ab + so, A + (size_t)(bm + r) * DW32 + k0 + ch0 * 4);
            cp16(bb + so, B + (size_t)(bn + r) * DW32 + k0 + ch0 * 4);
        }
    };

    float acc[4][4][4];
#pragma unroll
    for (int i = 0; i < 4; i++)
#pragma unroll
        for (int j = 0; j < 4; j++)
#pragma unroll
            for (int r = 0; r < 4; r++) acc[i][j][r] = 0.0f;

    issue_chunk(0, 0);
    asm volatile("cp.async.commit_group;");
    issue_chunk(1, 1);
    asm volatile("cp.async.commit_group;");

    for (int c = 0; c < GNCHUNK; c++) {
        asm volatile("cp.async.wait_group 1;");
        __syncthreads();
        if (c + 2 < GNCHUNK) issue_chunk(c + 2, (c + 2) % GNST);
        asm volatile("cp.async.commit_group;");

        const int buf = c % GNST;
        const uint32_t aaddr = as_a + (uint32_t)buf * GSTAGE * 4 +
                               (uint32_t)(((wm + a_lrow) * GSTR) + a_lcol) * 4;
        const uint32_t baddr = bs_a + (uint32_t)buf * GSTAGE * 4 +
                               (uint32_t)(((wn + b_lrow) * GSTR) + b_lcol) * 4;

        uint32_t af[2][4][4], bf[2][4][2];

        auto load_frags = [&](int kk, int d) {
#pragma unroll
            for (int mt = 0; mt < 4; mt++)
                ldsm4(af[d][mt][0], af[d][mt][1], af[d][mt][2], af[d][mt][3],
                      aaddr + (uint32_t)(mt * 16 * GSTR + kk) * 4);
#pragma unroll
            for (int u = 0; u < 2; u++)
                ldsm4(bf[d][2 * u][0], bf[d][2 * u][1],
                      bf[d][2 * u + 1][0], bf[d][2 * u + 1][1],
                      baddr + (uint32_t)(u * 16 * GSTR + kk) * 4);
        };

        load_frags(0, 0);
#pragma unroll
        for (int ks = 0; ks < 4; ks++) {
            const int cur = ks & 1;
            if (ks < 3) load_frags((ks + 1) * 8, cur ^ 1);
#pragma unroll
            for (int mt = 0; mt < 4; mt++)
#pragma unroll
                for (int nt = 0; nt < 4; nt++)
                    mma_f16(acc[mt][nt], af[cur][mt], bf[cur][nt]);
        }
    }

    const bool is_q = (MODE == 1) && (bnab < 1024);
    const bool is_v = (MODE == 1) && (bnab >= 2048);

#pragma unroll
    for (int mt = 0; mt < 4; mt++) {
        const int row0 = bm + wm + mt * 16 + gid;
#pragma unroll
        for (int nt = 0; nt < 4; nt++) {
            const int gcol = bn + wn + nt * 8 + 2 * tig;
#pragma unroll
            for (int half = 0; half < 2; half++) {
                const int row = row0 + 8 * half;
                float v0 = acc[mt][nt][2 * half];
                float v1 = acc[mt][nt][2 * half + 1];
                if (MODE == 0) {
                    *reinterpret_cast<float2*>(Cf + (size_t)row * DMODEL + gcol) =
                        make_float2(v0, v1);
                } else {
                    const int b = row >> 11;
                    const int l = row & (SEQ - 1);
                    const int h = gcol >> 6;
                    const int dd = gcol & (HDIM - 1);
                    const int bh = b * NHEAD + h;
                    if (is_v) {
                        Cvt[((size_t)bh * HDIM + dd) * SEQ + l] = hbits(v0);
                        Cvt[((size_t)bh * HDIM + dd + 1) * SEQ + l] = hbits(v1);
                    } else {
                        if (is_q) { v0 *= CEXPF; v1 *= CEXPF; }
                        uint32_t* dst = (is_q ? Cq : Ck);
                        dst[((size_t)bh * SEQ + l) * 32 + (dd >> 1)] = h2bits(v0, v1);
                    }
                }
            }
        }
    }
}

// ---------------------------------------------------------------------------
// Flash attention, fp16 mma.sync m16n8k16, causal.
// Q direct gmem->regs; 3-stage K / V^T cp.async ring, one sync per kb.
// K and V^T fragments via ldmatrix.x4. PV A-frags are own registers.
// ---------------------------------------------------------------------------
#define FA_BK 64
#define FA_STR 36
#define FA_ST (64 * FA_STR)
#define FA_SMEM_BYTES (6 * FA_ST * 4)   // 55296 B

__device__ __forceinline__ void fa_load_kv(uint32_t ks_a, uint32_t vs_a,
                                           const uint32_t* Kg, const uint16_t* Vtg,
                                           int k0, int stage, int tid) {
    const uint32_t ko = ks_a + (uint32_t)stage * (FA_ST * 4);
    const uint32_t vo = vs_a + (uint32_t)stage * (FA_ST * 4);
#pragma unroll
    for (int u = 0; u < 2; u++) {
        const int idx = u * 256 + tid;
        const int r = idx >> 3;
        const int ch = idx & 7;
        cp16(ko + (uint32_t)(r * FA_STR + ch * 4) * 4,
             Kg + (size_t)(k0 + r) * 32 + ch * 4);
        cp16(vo + (uint32_t)(r * FA_STR + ch * 4) * 4,
             Vtg + (size_t)r * SEQ + k0 + ch * 8);
    }
}

__global__ __launch_bounds__(256, 2) void flash_mma(const uint32_t* __restrict__ Q,
                                                    const uint32_t* __restrict__ K,
                                                    const uint16_t* __restrict__ Vt,
                                                    uint32_t* __restrict__ ctx) {
    extern __shared__ uint32_t fs32[];
    uint32_t* Ks = fs32;
    uint32_t* Vs = fs32 + 3 * FA_ST;

    const int tid = threadIdx.x;
    const int w = tid >> 5;
    const int lane = tid & 31;
    const int gid = lane >> 2;
    const int tig = lane & 3;
    const int bh = blockIdx.y;
    const int qb = (int)gridDim.x - 1 - (int)blockIdx.x;
    const int q0 = qb * 128;

    // LDSM lane->address mapping (B-operand pattern)
    const int b_lrow = (lane & 7) + (lane >> 4) * 8;
    const int b_lcol = ((lane >> 3) & 1) * 4;

    const uint32_t* Qg = Q + ((size_t)bh * SEQ + q0) * 32;
    const uint32_t* Kg = K + (size_t)bh * SEQ * 32;
    const uint16_t* Vtg = Vt + (size_t)bh * HDIM * SEQ;

    const uint32_t ks_a = smem_u32(Ks);
    const uint32_t vs_a = smem_u32(Vs);

    const int nkb = 2 * qb + 2;
    const int rq = 16 * w + gid;

    fa_load_kv(ks_a, vs_a, Kg, Vtg, 0, 0, tid);
    asm volatile("cp.async.commit_group;");
    if (nkb > 1) fa_load_kv(ks_a, vs_a, Kg, Vtg, FA_BK, 1, tid);
    asm volatile("cp.async.commit_group;");

    uint32_t qa_all[4][4];
#pragma unroll
    for (int g = 0; g < 4; g++) {
        qa_all[g][0] = Qg[(size_t)rq * 32 + 8 * g + tig];
        qa_all[g][1] = Qg[(size_t)(rq + 8) * 32 + 8 * g + tig];
        qa_all[g][2] = Qg[(size_t)rq * 32 + 8 * g + tig + 4];
        qa_all[g][3] = Qg[(size_t)(rq + 8) * 32 + 8 * g + tig + 4];
    }

    float o[8][4];
#pragma unroll
    for (int nt = 0; nt < 8; nt++)
#pragma unroll
        for (int e = 0; e < 4; e++) o[nt][e] = 0.0f;
    float m0 = -1e30f, m1 = -1e30f, l0 = 0.0f, l1 = 0.0f;

    for (int kb = 0; kb < nkb; kb++) {
        asm volatile("cp.async.wait_group 1;");
        __syncthreads();
        if (kb + 2 < nkb) fa_load_kv(ks_a, vs_a, Kg, Vtg, (kb + 2) * FA_BK, (kb + 2) % 3, tid);
        asm volatile("cp.async.commit_group;");

        const int buf = kb % 3;
        const uint32_t kaddr = ks_a + (uint32_t)buf * FA_ST * 4 +
                               (uint32_t)(b_lrow * FA_STR + b_lcol) * 4;
        const uint32_t vaddr = vs_a + (uint32_t)buf * FA_ST * 4 +
                               (uint32_t)(b_lrow * FA_STR + b_lcol) * 4;

        // --- S = Q K^T (16 x 64 per warp) ---
        float c[8][4];
#pragma unroll
        for (int nt = 0; nt < 8; nt++)
#pragma unroll
            for (int e = 0; e < 4; e++) c[nt][e] = 0.0f;

#pragma unroll
        for (int g = 0; g < 4; g++) {
            uint32_t kf[8][2];
#pragma unroll
            for (int u = 0; u < 4; u++)
                ldsm4(kf[2 * u][0], kf[2 * u][1], kf[2 * u + 1][0], kf[2 * u + 1][1],
                      kaddr + (uint32_t)(u * 16 * FA_STR + 8 * g) * 4);
#pragma unroll
            for (int nt = 0; nt < 8; nt++) mma_f16(c[nt], qa_all[g], kf[nt]);
        }

        // --- causal mask (log2-units; scale pre-folded into q) ---
        const int k0 = kb * FA_BK;
        if (k0 + 63 > q0 + 16 * w) {
            const int r0g = q0 + rq;
#pragma unroll
            for (int nt = 0; nt < 8; nt++) {
                const int cb = k0 + 8 * nt + 2 * tig;
                if (cb > r0g) c[nt][0] = -1e30f;
                if (cb + 1 > r0g) c[nt][1] = -1e30f;
                if (cb > r0g + 8) c[nt][2] = -1e30f;
                if (cb + 1 > r0g + 8) c[nt][3] = -1e30f;
            }
        }

        // --- online softmax ---
        float mx0 = -1e30f, mx1 = -1e30f;
#pragma unroll
        for (int nt = 0; nt < 8; nt++) {
            mx0 = fmaxf(mx0, fmaxf(c[nt][0], c[nt][1]));
            mx1 = fmaxf(mx1, fmaxf(c[nt][2], c[nt][3]));
        }
        mx0 = fmaxf(mx0, __shfl_xor_sync(0xffffffffu, mx0, 1));
        mx0 = fmaxf(mx0, __shfl_xor_sync(0xffffffffu, mx0, 2));
        mx1 = fmaxf(mx1, __shfl_xor_sync(0xffffffffu, mx1, 1));
        mx1 = fmaxf(mx1, __shfl_xor_sync(0xffffffffu, mx1, 2));

        const float mn0 = fmaxf(fmaxf(m0, mx0), -1000.0f);
        const float mn1 = fmaxf(fmaxf(m1, mx1), -1000.0f);
        const float corr0 = ex2(m0 - mn0);
        const float corr1 = ex2(m1 - mn1);

        float rs0 = 0.0f, rs1 = 0.0f;
        uint32_t pw[8][2];
#pragma unroll
        for (int nt = 0; nt < 8; nt++) {
            const float p0 = ex2(c[nt][0] - mn0);
            const float p1 = ex2(c[nt][1] - mn0);
            const float p2 = ex2(c[nt][2] - mn1);
            const float p3 = ex2(c[nt][3] - mn1);
            rs0 += p0 + p1;
            rs1 += p2 + p3;
            pw[nt][0] = h2bits(p0, p1);
            pw[nt][1] = h2bits(p2, p3);
        }
        rs0 += __shfl_xor_sync(0xffffffffu, rs0, 1);
        rs0 += __shfl_xor_sync(0xffffffffu, rs0, 2);
        rs1 += __shfl_xor_sync(0xffffffffu, rs1, 1);
        rs1 += __shfl_xor_sync(0xffffffffu, rs1, 2);

        l0 = l0 * corr0 + rs0;
        l1 = l1 * corr1 + rs1;
        m0 = mn0;
        m1 = mn1;

#pragma unroll
        for (int nt = 0; nt < 8; nt++) {
            o[nt][0] *= corr0;
            o[nt][1] *= corr0;
            o[nt][2] *= corr1;
            o[nt][3] *= corr1;
        }

        // --- O += P V : A-frags are own registers; V^T frags via LDSM ---
#pragma unroll
        for (int j = 0; j < 4; j++) {
            uint32_t pa[4] = {pw[2 * j][0], pw[2 * j][1],
                              pw[2 * j + 1][0], pw[2 * j + 1][1]};
            uint32_t vf[8][2];
#pragma unroll
            for (int u = 0; u < 4; u++)
                ldsm4(vf[2 * u][0], vf[2 * u][1], vf[2 * u + 1][0], vf[2 * u + 1][1],
                      vaddr + (uint32_t)(u * 16 * FA_STR + 8 * j) * 4);
#pragma unroll
            for (int nt = 0; nt < 8; nt++) mma_f16(o[nt], pa, vf[nt]);
        }
    }

    // normalize + write ctx half2-packed, (B, L, D/2) layout
    const float inv0 = 1.0f / l0;
    const float inv1 = 1.0f / l1;
    const int b = bh >> 4;
    const int h = bh & 15;
    const int r0 = q0 + rq;
#pragma unroll
    for (int nt = 0; nt < 8; nt++) {
        const int ci = h * 32 + 4 * nt + tig;
        ctx[((size_t)(b * SEQ + r0)) * DW32 + ci] = h2bits(o[nt][0] * inv0, o[nt][1] * inv0);
        ctx[((size_t)(b * SEQ + r0 + 8)) * DW32 + ci] = h2bits(o[nt][2] * inv1, o[nt][3] * inv1);
    }
}

// ---------------------------------------------------------------------------
// Launch
// ---------------------------------------------------------------------------
template <typename T>
static T* sym_addr(const void* symbol) {
    void* p = nullptr;
    cudaGetSymbolAddress(&p, symbol);
    return reinterpret_cast<T*>(p);
}

extern "C" void kernel_launch(void* const* d_in, const int* in_sizes, int n_in,
                              void* d_out, int out_size) {
    const float* x  = (const float*)d_in[0];
    const float* Wq = (const float*)d_in[1];
    const float* Wk = (const float*)d_in[2];
    const float* Wv = (const float*)d_in[3];
    const float* Wo = (const float*)d_in[4];
    float* out = (float*)d_out;

    uint32_t* xr = sym_addr<uint32_t>(g_xr);
    uint32_t* wq = sym_addr<uint32_t>(g_wq);
    uint32_t* wk = sym_addr<uint32_t>(g_wk);
    uint32_t* wv = sym_addr<uint32_t>(g_wv);
    uint32_t* wo = sym_addr<uint32_t>(g_wo);
    uint32_t* q  = sym_addr<uint32_t>(g_q);
    uint32_t* k  = sym_addr<uint32_t>(g_k);
    uint16_t* vt = sym_addr<uint16_t>(g_vt);
    uint32_t* ctx = sym_addr<uint32_t>(g_ctx);

    cudaFuncSetAttribute(gemm_mma<1>, cudaFuncAttributeMaxDynamicSharedMemorySize, GSMEM_BYTES);
    cudaFuncSetAttribute(gemm_mma<0>, cudaFuncAttributeMaxDynamicSharedMemorySize, GSMEM_BYTES);
    cudaFuncSetAttribute(flash_mma, cudaFuncAttributeMaxDynamicSharedMemorySize, FA_SMEM_BYTES);

    round_pack<<<(TOTAL4 + 255) / 256, 256>>>(x, Wq, Wk, Wv, Wo);

    dim3 gqkv(3 * DMODEL / 128, MTOT / 128);   // (24, 32)
    gemm_mma<1><<<gqkv, 256, GSMEM_BYTES>>>(xr, wq, wk, wv, nullptr, q, k, vt);

    dim3 ga(SEQ / 128, BATCH * NHEAD);         // (16, 32)
    flash_mma<<<ga, 256, FA_SMEM_BYTES>>>(q, k, vt, ctx);

    dim3 go(DMODEL / 128, MTOT / 128);         // (8, 32)
    gemm_mma<0><<<go, 256, GSMEM_BYTES>>>(ctx, wo, nullptr, nullptr, out, nullptr, nullptr, nullptr);
}